// round 13
// baseline (speedup 1.0000x reference)
#include <cuda_runtime.h>
#include <math.h>

#define NROWS 8192
#define KDIM  512
#define DDIM  256

// ---------------- scratch (no cudaMalloc allowed) ----------------
__device__ float g_Wh[NROWS * DDIM];   // 8 MB
__device__ float g_Wh1[NROWS];
__device__ float g_Wh2[NROWS];

// ---------------- f32x2 packed-FMA helpers (Blackwell) ----------------
__device__ __forceinline__ unsigned long long dup2f(float x) {
    unsigned long long r;
    asm("mov.b64 %0, {%1, %1};" : "=l"(r) : "f"(x));
    return r;
}
__device__ __forceinline__ unsigned long long ffma2(unsigned long long a,
                                                    unsigned long long b,
                                                    unsigned long long c) {
    unsigned long long d;
    asm("fma.rn.f32x2 %0, %1, %2, %3;" : "=l"(d) : "l"(a), "l"(b), "l"(c));
    return d;
}
__device__ __forceinline__ float2 unpack2(unsigned long long v) {
    float x, y;
    asm("mov.b64 {%0, %1}, %2;" : "=f"(x), "=f"(y) : "l"(v));
    return make_float2(x, y);
}

// ---------------- cp.async helpers ----------------
__device__ __forceinline__ void cp16(void* s, const void* g) {
    unsigned sa = (unsigned)__cvta_generic_to_shared(s);
    asm volatile("cp.async.cg.shared.global [%0], [%1], 16;" :: "r"(sa), "l"(g));
}
__device__ __forceinline__ void cp_commit() { asm volatile("cp.async.commit_group;"); }
__device__ __forceinline__ void cp_wait0()  { asm volatile("cp.async.wait_group 0;" ::: "memory"); }

// =====================================================================
// Kernel 1: Wh = input[8192,512] @ weight[512,256]
// 128x128 block tile, 8x8 micro tile, f32x2 accumulators, double-buffered.
// grid (2, 64), 256 threads.
// =====================================================================
__global__ void __launch_bounds__(256) k_gemm_wh(const float* __restrict__ A,
                                                 const float* __restrict__ B) {
    __shared__ __align__(16) float As[2][8][132];   // transposed [k][m], padded
    __shared__ __align__(16) float Bs[2][8][128];

    const int t   = threadIdx.x;
    const int m0g = blockIdx.y * 128;
    const int n0g = blockIdx.x * 128;

    const int arow = t >> 1, ac4 = (t & 1) * 4;     // A tile: 128 rows x 8 cols
    const int brow = t >> 5, bc  = (t & 31) * 4;    // B tile: 8 rows x 128 cols

    // ---- prologue: tile 0 ----
    float4 aReg = *(const float4*)&A[(size_t)(m0g + arow) * KDIM + ac4];
    cp16(&Bs[0][brow][bc], &B[(size_t)brow * DDIM + n0g + bc]);
    cp_commit();
#pragma unroll
    for (int i = 0; i < 4; i++) As[0][ac4 + i][arow] = ((const float*)&aReg)[i];
    cp_wait0();
    __syncthreads();

    unsigned long long acc[8][4];
#pragma unroll
    for (int i = 0; i < 8; i++)
#pragma unroll
        for (int j = 0; j < 4; j++) acc[i][j] = 0ull;

    const int m0 = (t >> 4) * 8, n0 = (t & 15) * 8;

    for (int kt = 0; kt < KDIM / 8; ++kt) {
        const int cur = kt & 1, nxt = cur ^ 1;
        float4 aN;
        if (kt < KDIM / 8 - 1) {
            aN = *(const float4*)&A[(size_t)(m0g + arow) * KDIM + (kt + 1) * 8 + ac4];
            cp16(&Bs[nxt][brow][bc], &B[(size_t)((kt + 1) * 8 + brow) * DDIM + n0g + bc]);
            cp_commit();
        }
#pragma unroll
        for (int kk = 0; kk < 8; kk++) {
            float4 a_lo = *(const float4*)&As[cur][kk][m0];
            float4 a_hi = *(const float4*)&As[cur][kk][m0 + 4];
            ulonglong2 b01 = *(const ulonglong2*)&Bs[cur][kk][n0];
            ulonglong2 b23 = *(const ulonglong2*)&Bs[cur][kk][n0 + 4];
            float av[8] = {a_lo.x, a_lo.y, a_lo.z, a_lo.w, a_hi.x, a_hi.y, a_hi.z, a_hi.w};
#pragma unroll
            for (int i = 0; i < 8; i++) {
                unsigned long long pd = dup2f(av[i]);
                acc[i][0] = ffma2(pd, b01.x, acc[i][0]);
                acc[i][1] = ffma2(pd, b01.y, acc[i][1]);
                acc[i][2] = ffma2(pd, b23.x, acc[i][2]);
                acc[i][3] = ffma2(pd, b23.y, acc[i][3]);
            }
        }
        if (kt < KDIM / 8 - 1) {
#pragma unroll
            for (int i = 0; i < 4; i++) As[nxt][ac4 + i][arow] = ((const float*)&aN)[i];
        }
        cp_wait0();
        __syncthreads();
    }

    // ---- epilogue ----
#pragma unroll
    for (int i = 0; i < 8; i++) {
        float2 p0 = unpack2(acc[i][0]);
        float2 p1 = unpack2(acc[i][1]);
        float2 p2 = unpack2(acc[i][2]);
        float2 p3 = unpack2(acc[i][3]);
        size_t off = (size_t)(m0g + m0 + i) * DDIM + n0g + n0;
        *(float4*)&g_Wh[off]     = make_float4(p0.x, p0.y, p1.x, p1.y);
        *(float4*)&g_Wh[off + 4] = make_float4(p2.x, p2.y, p3.x, p3.y);
    }
}

// =====================================================================
// Kernel 2: Wh1 = Wh @ a[0:256], Wh2 = Wh @ a[256:512]. One warp per row.
// =====================================================================
__global__ void __launch_bounds__(256) k_rowdots(const float* __restrict__ avec) {
    const int row  = blockIdx.x * 8 + (threadIdx.x >> 5);
    const int lane = threadIdx.x & 31;
    const float4* wr = (const float4*)&g_Wh[(size_t)row * DDIM];
    float4 v0 = wr[lane], v1 = wr[lane + 32];
    const float4* aa = (const float4*)avec;
    float4 u0 = aa[lane], u1 = aa[lane + 32], u2 = aa[lane + 64], u3 = aa[lane + 96];
    float s1 = v0.x * u0.x + v0.y * u0.y + v0.z * u0.z + v0.w * u0.w
             + v1.x * u1.x + v1.y * u1.y + v1.z * u1.z + v1.w * u1.w;
    float s2 = v0.x * u2.x + v0.y * u2.y + v0.z * u2.z + v0.w * u2.w
             + v1.x * u3.x + v1.y * u3.y + v1.z * u3.z + v1.w * u3.w;
#pragma unroll
    for (int o = 16; o; o >>= 1) {
        s1 += __shfl_xor_sync(0xffffffffu, s1, o);
        s2 += __shfl_xor_sync(0xffffffffu, s2, o);
    }
    if (lane == 0) { g_Wh1[row] = s1; g_Wh2[row] = s2; }
}

// =====================================================================
// Kernel 3: fused masked-softmax attention + PV + ELU.
// BM=64 rows per CTA, BN=64 column tile, 128 CTAs (1 wave), 256 threads.
// No max subtraction needed (bounded logits; masked terms are exactly 0,
// matching exp(-9e15 - max) == 0 in the reference).
// Double-buffered cp.async for adj / Wh / Wh2 tiles.
// =====================================================================
// dynamic smem layout (bytes):
//   WhS  [2][64][256] f32 : 0      .. 131072
//   AdjS [2][64][64]  i32 : 131072 .. 163840
//   Ps   [64][68]     f32 : 163840 .. 181248
//   Wh1S [64]         f32 : 181248 .. 181504
//   Wh2S [2][64]      f32 : 181504 .. 182016
//   LS   [64]         f32 : 182016 .. 182272
#define K2_SMEM 182272

__global__ void __launch_bounds__(256) k_attn(const int* __restrict__ adj,
                                              float* __restrict__ out) {
    extern __shared__ char smraw[];
    float* WhS  = (float*)smraw;
    int*   AdjS = (int*)(smraw + 131072);
    float* Ps   = (float*)(smraw + 163840);
    float* Wh1S = (float*)(smraw + 181248);
    float* Wh2S = (float*)(smraw + 181504);
    float* LS   = (float*)(smraw + 182016);

    const int t     = threadIdx.x;
    const int m0blk = blockIdx.x * 64;

    auto prefetch = [&](int jb, int nb) {
#pragma unroll
        for (int i = 0; i < 16; i++) {                  // Wh tile 64x256 f32
            int idx = t + i * 256;
            int row = idx >> 6, c4 = (idx & 63) << 2;
            cp16(&WhS[nb * 16384 + row * 256 + c4],
                 &g_Wh[((size_t)jb * 64 + row) * 256 + c4]);
        }
#pragma unroll
        for (int i = 0; i < 4; i++) {                   // adj tile 64x64 i32
            int idx = t + i * 256;
            int row = idx >> 4, c4 = (idx & 15) << 2;
            cp16(&AdjS[nb * 4096 + row * 64 + c4],
                 &adj[(size_t)(m0blk + row) * NROWS + jb * 64 + c4]);
        }
        if (t < 16)                                      // Wh2 tile 64 f32
            cp16(&Wh2S[nb * 64 + t * 4], &g_Wh2[jb * 64 + t * 4]);
    };

    // prologue
    prefetch(0, 0);
    cp_commit();
    if (t < 64) Wh1S[t] = g_Wh1[m0blk + t];
    cp_wait0();
    __syncthreads();

    float lp[16];
#pragma unroll
    for (int i = 0; i < 16; i++) lp[i] = 0.f;

    unsigned long long acc[8][4];
#pragma unroll
    for (int i = 0; i < 8; i++)
#pragma unroll
        for (int j = 0; j < 4; j++) acc[i][j] = 0ull;

    const int gA = t >> 6, laneA = t & 63;       // phase-A map (row-stable)
    const int m0 = (t >> 5) * 8, d0 = (t & 31) * 8;  // phase-B map

    for (int jb = 0; jb < NROWS / 64; ++jb) {
        const int cur = jb & 1, nxt = cur ^ 1;
        if (jb < NROWS / 64 - 1) { prefetch(jb + 1, nxt); cp_commit(); }

        // ---- phase A: p = adj ? exp(leaky(Wh1_i + Wh2_j)) : 0 ----
        {
            const int*   ad  = &AdjS[cur * 4096];
            const float  w2  = Wh2S[cur * 64 + laneA];
#pragma unroll
            for (int mm = 0; mm < 16; ++mm) {
                int   m = gA * 16 + mm;
                int   av = ad[m * 64 + laneA];
                float e  = Wh1S[m] + w2;
                e = fmaxf(e, 0.2f * e);                 // LeakyReLU(0.2)
                float p = (av > 0) ? __expf(e) : 0.f;
                lp[mm] += p;
                Ps[m * 68 + laneA] = p;
            }
        }
        __syncthreads();

        // ---- phase B: acc += P_tile @ Wh_tile (f32x2 packed FMA) ----
        {
            const float* whb = &WhS[cur * 16384];
#pragma unroll 1
            for (int j4 = 0; j4 < 16; ++j4) {
                float4 pv[8];
#pragma unroll
                for (int i = 0; i < 8; i++)
                    pv[i] = *(const float4*)&Ps[(m0 + i) * 68 + j4 * 4];
#pragma unroll
                for (int jj = 0; jj < 4; jj++) {
                    const float* wr = &whb[(j4 * 4 + jj) * 256 + d0];
                    ulonglong2 wA = *(const ulonglong2*)wr;
                    ulonglong2 wB = *(const ulonglong2*)(wr + 4);
#pragma unroll
                    for (int i = 0; i < 8; i++) {
                        float p = ((const float*)&pv[i])[jj];
                        unsigned long long pd = dup2f(p);
                        acc[i][0] = ffma2(pd, wA.x, acc[i][0]);
                        acc[i][1] = ffma2(pd, wA.y, acc[i][1]);
                        acc[i][2] = ffma2(pd, wB.x, acc[i][2]);
                        acc[i][3] = ffma2(pd, wB.y, acc[i][3]);
                    }
                }
            }
        }
        cp_wait0();
        __syncthreads();
    }

    // ---- row-sum reduction (reuse Ps) ----
#pragma unroll
    for (int mm = 0; mm < 16; ++mm) Ps[(gA * 16 + mm) * 68 + laneA] = lp[mm];
    __syncthreads();
    if (t < 64) {
        float s = 0.f;
#pragma unroll 8
        for (int j = 0; j < 64; ++j) s += Ps[t * 68 + j];
        LS[t] = 1.0f / s;
    }
    __syncthreads();

    // ---- epilogue: out = elu(acc / l) ----
#pragma unroll
    for (int i = 0; i < 8; i++) {
        int   m = m0 + i;
        float r = LS[m];
        float v[8];
#pragma unroll
        for (int dd = 0; dd < 4; dd++) {
            float2 u = unpack2(acc[i][dd]);
            v[2 * dd] = u.x; v[2 * dd + 1] = u.y;
        }
#pragma unroll
        for (int k = 0; k < 8; k++) {
            float x = v[k] * r;
            v[k] = (x > 0.f) ? x : expm1f(x);
        }
        size_t off = (size_t)(m0blk + m) * DDIM + d0;
        *(float4*)&out[off]     = make_float4(v[0], v[1], v[2], v[3]);
        *(float4*)&out[off + 4] = make_float4(v[4], v[5], v[6], v[7]);
    }
}

// =====================================================================
extern "C" void kernel_launch(void* const* d_in, const int* in_sizes, int n_in,
                              void* d_out, int out_size) {
    const float* input  = (const float*)d_in[0];   // [8192,512]
    const int*   adj    = (const int*)d_in[1];     // [8192,8192]
    const float* weight = (const float*)d_in[2];   // [512,256]
    const float* avec   = (const float*)d_in[3];   // [512,1]
    float* out = (float*)d_out;                    // [8192,256]

    cudaFuncSetAttribute((const void*)k_attn,
                         cudaFuncAttributeMaxDynamicSharedMemorySize, K2_SMEM);

    k_gemm_wh<<<dim3(2, 64), 256>>>(input, weight);
    k_rowdots<<<NROWS / 8, 256>>>(avec);
    k_attn<<<NROWS / 64, 256, K2_SMEM>>>(adj, out);
}

// round 17
// speedup vs baseline: 2.0739x; 2.0739x over previous
#include <cuda_runtime.h>
#include <math.h>
#include <stdint.h>

#define NROWS 8192
#define KDIM  512
#define DDIM  256

// ---------------- scratch (no cudaMalloc allowed) ----------------
__device__ float g_Wh[NROWS * DDIM];                  // 8 MB fp32 Wh
__device__ float g_Wh1[NROWS];
__device__ float g_Wh2[NROWS];
__device__ unsigned short g_WhT_hi[DDIM * NROWS];     // 4 MB bf16 Wh^T hi  [d][j]
__device__ unsigned short g_WhT_lo[DDIM * NROWS];     // 4 MB bf16 Wh^T lo  [d][j]

// ---------------- f32x2 packed-FMA helpers ----------------
__device__ __forceinline__ unsigned long long dup2f(float x) {
    unsigned long long r;
    asm("mov.b64 %0, {%1, %1};" : "=l"(r) : "f"(x));
    return r;
}
__device__ __forceinline__ unsigned long long ffma2(unsigned long long a,
                                                    unsigned long long b,
                                                    unsigned long long c) {
    unsigned long long d;
    asm("fma.rn.f32x2 %0, %1, %2, %3;" : "=l"(d) : "l"(a), "l"(b), "l"(c));
    return d;
}
__device__ __forceinline__ float2 unpack2(unsigned long long v) {
    float x, y;
    asm("mov.b64 {%0, %1}, %2;" : "=f"(x), "=f"(y) : "l"(v));
    return make_float2(x, y);
}

// ---------------- cp.async helpers ----------------
__device__ __forceinline__ void cp16(void* s, const void* g) {
    unsigned sa = (unsigned)__cvta_generic_to_shared(s);
    asm volatile("cp.async.cg.shared.global [%0], [%1], 16;" :: "r"(sa), "l"(g));
}
__device__ __forceinline__ void cp16s(uint32_t s, const void* g) {
    asm volatile("cp.async.cg.shared.global [%0], [%1], 16;" :: "r"(s), "l"(g));
}
__device__ __forceinline__ void cp_commit() { asm volatile("cp.async.commit_group;"); }
__device__ __forceinline__ void cp_wait0()  { asm volatile("cp.async.wait_group 0;" ::: "memory"); }

__device__ __forceinline__ uint32_t smem_u32(const void* p) {
    uint32_t a;
    asm("{ .reg .u64 t; cvta.to.shared.u64 t, %1; cvt.u32.u64 %0, t; }" : "=r"(a) : "l"(p));
    return a;
}

// pack two fp32 -> bf16x2 (first arg in low 16 bits)
__device__ __forceinline__ uint32_t pack_bf16x2(float lo_el, float hi_el) {
    uint32_t r;
    asm("cvt.rn.satfinite.bf16x2.f32 %0, %1, %2;" : "=r"(r) : "f"(hi_el), "f"(lo_el));
    return r;
}

// ---------------- ldmatrix / mma.sync (legacy tensor path, sm_80+) ----------------
__device__ __forceinline__ void ldsm4(uint32_t* r, uint32_t a) {
    asm volatile("ldmatrix.sync.aligned.m8n8.x4.shared.b16 {%0,%1,%2,%3}, [%4];"
                 : "=r"(r[0]), "=r"(r[1]), "=r"(r[2]), "=r"(r[3]) : "r"(a));
}
__device__ __forceinline__ void mma_bf16(float* c, const uint32_t* a, const uint32_t* b) {
    asm volatile("mma.sync.aligned.m16n8k16.row.col.f32.bf16.bf16.f32 "
                 "{%0,%1,%2,%3}, {%4,%5,%6,%7}, {%8,%9}, {%0,%1,%2,%3};"
                 : "+f"(c[0]), "+f"(c[1]), "+f"(c[2]), "+f"(c[3])
                 : "r"(a[0]), "r"(a[1]), "r"(a[2]), "r"(a[3]), "r"(b[0]), "r"(b[1]));
}

// =====================================================================
// Kernel 1: Wh = input @ weight ; also emits Wh^T as bf16 hi/lo splits.
// =====================================================================
__global__ void __launch_bounds__(256) k_gemm_wh(const float* __restrict__ A,
                                                 const float* __restrict__ B) {
    __shared__ __align__(16) float As[2][8][132];
    __shared__ __align__(16) float Bs[2][8][128];

    const int t   = threadIdx.x;
    const int m0g = blockIdx.y * 128;
    const int n0g = blockIdx.x * 128;

    const int arow = t >> 1, ac4 = (t & 1) * 4;
    const int brow = t >> 5, bc  = (t & 31) * 4;

    float4 aReg = *(const float4*)&A[(size_t)(m0g + arow) * KDIM + ac4];
    cp16(&Bs[0][brow][bc], &B[(size_t)brow * DDIM + n0g + bc]);
    cp_commit();
#pragma unroll
    for (int i = 0; i < 4; i++) As[0][ac4 + i][arow] = ((const float*)&aReg)[i];
    cp_wait0();
    __syncthreads();

    unsigned long long acc[8][4];
#pragma unroll
    for (int i = 0; i < 8; i++)
#pragma unroll
        for (int j = 0; j < 4; j++) acc[i][j] = 0ull;

    const int m0 = (t >> 4) * 8, n0 = (t & 15) * 8;

    for (int kt = 0; kt < KDIM / 8; ++kt) {
        const int cur = kt & 1, nxt = cur ^ 1;
        float4 aN;
        if (kt < KDIM / 8 - 1) {
            aN = *(const float4*)&A[(size_t)(m0g + arow) * KDIM + (kt + 1) * 8 + ac4];
            cp16(&Bs[nxt][brow][bc], &B[(size_t)((kt + 1) * 8 + brow) * DDIM + n0g + bc]);
            cp_commit();
        }
#pragma unroll
        for (int kk = 0; kk < 8; kk++) {
            float4 a_lo = *(const float4*)&As[cur][kk][m0];
            float4 a_hi = *(const float4*)&As[cur][kk][m0 + 4];
            ulonglong2 b01 = *(const ulonglong2*)&Bs[cur][kk][n0];
            ulonglong2 b23 = *(const ulonglong2*)&Bs[cur][kk][n0 + 4];
            float av[8] = {a_lo.x, a_lo.y, a_lo.z, a_lo.w, a_hi.x, a_hi.y, a_hi.z, a_hi.w};
#pragma unroll
            for (int i = 0; i < 8; i++) {
                unsigned long long pd = dup2f(av[i]);
                acc[i][0] = ffma2(pd, b01.x, acc[i][0]);
                acc[i][1] = ffma2(pd, b01.y, acc[i][1]);
                acc[i][2] = ffma2(pd, b23.x, acc[i][2]);
                acc[i][3] = ffma2(pd, b23.y, acc[i][3]);
            }
        }
        if (kt < KDIM / 8 - 1) {
#pragma unroll
            for (int i = 0; i < 4; i++) As[nxt][ac4 + i][arow] = ((const float*)&aN)[i];
        }
        cp_wait0();
        __syncthreads();
    }

    // epilogue: fp32 Wh + bf16 hi/lo transposed tiles
    float v[8][8];
#pragma unroll
    for (int i = 0; i < 8; i++) {
#pragma unroll
        for (int q = 0; q < 4; q++) {
            float2 u = unpack2(acc[i][q]);
            v[i][2 * q] = u.x; v[i][2 * q + 1] = u.y;
        }
        size_t off = (size_t)(m0g + m0 + i) * DDIM + n0g + n0;
        *(float4*)&g_Wh[off]     = make_float4(v[i][0], v[i][1], v[i][2], v[i][3]);
        *(float4*)&g_Wh[off + 4] = make_float4(v[i][4], v[i][5], v[i][6], v[i][7]);
    }
#pragma unroll
    for (int dd = 0; dd < 8; dd++) {
        uint32_t hw[4], lw[4];
#pragma unroll
        for (int q = 0; q < 4; q++) {
            float x0 = v[2 * q][dd], x1 = v[2 * q + 1][dd];
            uint32_t hp = pack_bf16x2(x0, x1);
            float h0 = __uint_as_float(hp << 16);
            float h1 = __uint_as_float(hp & 0xffff0000u);
            hw[q] = hp;
            lw[q] = pack_bf16x2(x0 - h0, x1 - h1);
        }
        size_t o = (size_t)(n0g + n0 + dd) * NROWS + (m0g + m0);
        *(uint4*)(g_WhT_hi + o) = make_uint4(hw[0], hw[1], hw[2], hw[3]);
        *(uint4*)(g_WhT_lo + o) = make_uint4(lw[0], lw[1], lw[2], lw[3]);
    }
}

// =====================================================================
// Kernel 2: row dots
// =====================================================================
__global__ void __launch_bounds__(256) k_rowdots(const float* __restrict__ avec) {
    const int row  = blockIdx.x * 8 + (threadIdx.x >> 5);
    const int lane = threadIdx.x & 31;
    const float4* wr = (const float4*)&g_Wh[(size_t)row * DDIM];
    float4 v0 = wr[lane], v1 = wr[lane + 32];
    const float4* aa = (const float4*)avec;
    float4 u0 = aa[lane], u1 = aa[lane + 32], u2 = aa[lane + 64], u3 = aa[lane + 96];
    float s1 = v0.x * u0.x + v0.y * u0.y + v0.z * u0.z + v0.w * u0.w
             + v1.x * u1.x + v1.y * u1.y + v1.z * u1.z + v1.w * u1.w;
    float s2 = v0.x * u2.x + v0.y * u2.y + v0.z * u2.z + v0.w * u2.w
             + v1.x * u3.x + v1.y * u3.y + v1.z * u3.z + v1.w * u3.w;
#pragma unroll
    for (int o = 16; o; o >>= 1) {
        s1 += __shfl_xor_sync(0xffffffffu, s1, o);
        s2 += __shfl_xor_sync(0xffffffffu, s2, o);
    }
    if (lane == 0) { g_Wh1[row] = s1; g_Wh2[row] = s2; }
}

// =====================================================================
// Kernel 3: fused attention, PV on mma.sync bf16 (3-term split, fp32 acc).
// 128 CTAs (BM=64), 256 threads, each CTA walks all 128 j-tiles (K=64).
// smem (from 1024-aligned base):
//   Bs : [buf2][hi/lo][n=256][128B swz]   = 131072
//   Ps : [hi/lo][m=64][128B swz]          =  16384  @131072
//   W2 : 8192 f32                         =  32768  @147456
//   LS : 64 f32                           =    256  @180224
// =====================================================================
#define ATT_SMEM (180480 + 1024)

__global__ void __launch_bounds__(256, 1) k_attn(const int* __restrict__ adj,
                                                 float* __restrict__ out) {
    extern __shared__ char smraw[];
    char* smA = (char*)(((uintptr_t)smraw + 1023) & ~(uintptr_t)1023);
    const uint32_t smb = smem_u32(smA);
    const uint32_t BSb = smb;
    const uint32_t PSb = smb + 131072;
    float* W2f = (float*)(smA + 147456);
    float* LSf = (float*)(smA + 180224);

    const int t = threadIdx.x, wid = t >> 5, lane = t & 31;
    const int m0blk = blockIdx.x * 64;
    const int arow  = wid * 8;                 // phase-A rows for this warp
    const int n0w   = wid * 32;                // mma n-range for this warp

    // ---- prologue loads ----
#pragma unroll
    for (int i = 0; i < 8; i++)                // Wh2 -> smem (32 KB)
        cp16(W2f + (i * 256 + t) * 4, g_Wh2 + (i * 256 + t) * 4);
    // B tile 0
    {
#pragma unroll
        for (int h = 0; h < 2; h++) {
            const unsigned short* src = h ? g_WhT_lo : g_WhT_hi;
            const uint32_t base = BSb + (uint32_t)h * 32768;
#pragma unroll
            for (int it = 0; it < 8; it++) {
                int lin = t + it * 256;
                int d = lin >> 3, c = lin & 7;
                uint32_t off = (uint32_t)(d * 128 + ((c * 16) ^ ((d & 7) << 4)));
                cp16s(base + off, src + (size_t)d * NROWS + c * 8);
            }
        }
    }
    cp_commit();

    float w1[8];
#pragma unroll
    for (int mm = 0; mm < 8; mm++) w1[mm] = g_Wh1[m0blk + arow + mm];
    float lp[8];
#pragma unroll
    for (int mm = 0; mm < 8; mm++) lp[mm] = 0.f;

    // adj prefetch for tile 0
    int2 adjr[8];
    {
        const int* ap = adj + (size_t)(m0blk + arow) * NROWS + lane * 2;
#pragma unroll
        for (int mm = 0; mm < 8; mm++) adjr[mm] = *(const int2*)(ap + (size_t)mm * NROWS);
    }

    float acc[4][4][4];
#pragma unroll
    for (int a = 0; a < 4; a++)
#pragma unroll
        for (int b = 0; b < 4; b++)
#pragma unroll
            for (int c = 0; c < 4; c++) acc[a][b][c] = 0.f;

    cp_wait0();
    __syncthreads();

    const int r8  = lane & 7, sel = lane >> 3;

    for (int jt = 0; jt < 128; jt++) {
        const int buf = jt & 1;

        // ---- phase A: P tile (64x64) hi/lo bf16 into Ps ----
        {
            const int jg = jt * 64;
            float2 w2 = *(const float2*)(W2f + jg + lane * 2);
#pragma unroll
            for (int mm = 0; mm < 8; mm++) {
                const int m = arow + mm;
                int2 av = adjr[mm];
                float e0 = w1[mm] + w2.x;
                float e1 = w1[mm] + w2.y;
                float t0 = e0 * (e0 > 0.f ? 1.4426950408889634f : 0.28853900817779268f);
                float t1 = e1 * (e1 > 0.f ? 1.4426950408889634f : 0.28853900817779268f);
                float r0, r1;
                asm("ex2.approx.f32 %0, %1;" : "=f"(r0) : "f"(t0));
                asm("ex2.approx.f32 %0, %1;" : "=f"(r1) : "f"(t1));
                float p0 = (av.x > 0) ? r0 : 0.f;
                float p1 = (av.y > 0) ? r1 : 0.f;
                lp[mm] += p0 + p1;
                uint32_t hp = pack_bf16x2(p0, p1);
                float h0 = __uint_as_float(hp << 16);
                float h1 = __uint_as_float(hp & 0xffff0000u);
                uint32_t lo = pack_bf16x2(p0 - h0, p1 - h1);
                uint32_t off = (uint32_t)(m * 128 + ((lane * 4) ^ ((m & 7) << 4)));
                asm volatile("st.shared.b32 [%0], %1;" :: "r"(PSb + off), "r"(hp));
                asm volatile("st.shared.b32 [%0], %1;" :: "r"(PSb + 8192 + off), "r"(lo));
            }
        }
        // adj prefetch for next tile (latency hidden behind MMA)
        if (jt < 127) {
            const int* ap = adj + (size_t)(m0blk + arow) * NROWS + (jt + 1) * 64 + lane * 2;
#pragma unroll
            for (int mm = 0; mm < 8; mm++) adjr[mm] = *(const int2*)(ap + (size_t)mm * NROWS);
        }
        __syncthreads();                        // Ps visible to all warps

        // issue next B tile while MMA runs
        if (jt < 127) {
            const int jgN = (jt + 1) * 64;
            const uint32_t bb = BSb + (uint32_t)((buf ^ 1) * 65536);
#pragma unroll
            for (int h = 0; h < 2; h++) {
                const unsigned short* src = h ? g_WhT_lo : g_WhT_hi;
                const uint32_t base = bb + (uint32_t)h * 32768;
#pragma unroll
                for (int it = 0; it < 8; it++) {
                    int lin = t + it * 256;
                    int d = lin >> 3, c = lin & 7;
                    uint32_t off = (uint32_t)(d * 128 + ((c * 16) ^ ((d & 7) << 4)));
                    cp16s(base + off, src + (size_t)d * NROWS + jgN + c * 8);
                }
            }
            cp_commit();
        }

        // ---- phase B: acc += Ph*Bh + Ph*Bl + Pl*Bh  (mma.sync bf16) ----
        {
            const uint32_t pb  = PSb, plb = PSb + 8192;
            const uint32_t bbH = BSb + (uint32_t)(buf * 65536);
            const uint32_t bbL = bbH + 32768;
#pragma unroll
            for (int ks = 0; ks < 4; ks++) {
                const int kb = ks * 32;          // byte offset of k16 chunk
                uint32_t aH[4][4], aL[4][4];
#pragma unroll
                for (int mb = 0; mb < 4; mb++) {
                    int m = mb * 16 + (sel & 1) * 8 + r8;
                    uint32_t off = (uint32_t)(m * 128 +
                        ((kb + (sel >> 1) * 16) ^ ((m & 7) << 4)));
                    ldsm4(aH[mb], pb + off);
                    ldsm4(aL[mb], plb + off);
                }
                uint32_t bH[4][2], bL[4][2];
#pragma unroll
                for (int np = 0; np < 2; np++) {
                    int n = n0w + np * 16 + (sel >> 1) * 8 + r8;
                    uint32_t off = (uint32_t)(n * 128 +
                        ((kb + (sel & 1) * 16) ^ ((n & 7) << 4)));
                    uint32_t rh[4], rl[4];
                    ldsm4(rh, bbH + off);
                    ldsm4(rl, bbL + off);
                    bH[2 * np][0] = rh[0]; bH[2 * np][1] = rh[1];
                    bH[2 * np + 1][0] = rh[2]; bH[2 * np + 1][1] = rh[3];
                    bL[2 * np][0] = rl[0]; bL[2 * np][1] = rl[1];
                    bL[2 * np + 1][0] = rl[2]; bL[2 * np + 1][1] = rl[3];
                }
#pragma unroll
                for (int mb = 0; mb < 4; mb++)
#pragma unroll
                    for (int nb = 0; nb < 4; nb++) {
                        mma_bf16(acc[mb][nb], aH[mb], bH[nb]);
                        mma_bf16(acc[mb][nb], aH[mb], bL[nb]);
                        mma_bf16(acc[mb][nb], aL[mb], bH[nb]);
                    }
            }
        }
        cp_wait0();
        __syncthreads();                         // B(next) ready; Ps free
    }

    // ---- row sums -> reciprocal in smem ----
#pragma unroll
    for (int mm = 0; mm < 8; mm++) {
        float s = lp[mm];
#pragma unroll
        for (int o = 16; o; o >>= 1) s += __shfl_xor_sync(0xffffffffu, s, o);
        if (lane == 0) LSf[arow + mm] = 1.0f / s;
    }
    __syncthreads();

    // ---- epilogue: out = elu(acc / l) ----
    const int qrow = lane >> 2, qcol = (lane & 3) * 2;
#pragma unroll
    for (int mb = 0; mb < 4; mb++) {
        const int m0 = mb * 16 + qrow;
        const float rv0 = LSf[m0], rv1 = LSf[m0 + 8];
#pragma unroll
        for (int nb = 0; nb < 4; nb++) {
            const int n = n0w + nb * 8 + qcol;
            float x0 = acc[mb][nb][0] * rv0;
            float x1 = acc[mb][nb][1] * rv0;
            float x2 = acc[mb][nb][2] * rv1;
            float x3 = acc[mb][nb][3] * rv1;
            x0 = (x0 > 0.f) ? x0 : expm1f(x0);
            x1 = (x1 > 0.f) ? x1 : expm1f(x1);
            x2 = (x2 > 0.f) ? x2 : expm1f(x2);
            x3 = (x3 > 0.f) ? x3 : expm1f(x3);
            *(float2*)(out + (size_t)(m0blk + m0) * DDIM + n)     = make_float2(x0, x1);
            *(float2*)(out + (size_t)(m0blk + m0 + 8) * DDIM + n) = make_float2(x2, x3);
        }
    }
}

// =====================================================================
extern "C" void kernel_launch(void* const* d_in, const int* in_sizes, int n_in,
                              void* d_out, int out_size) {
    const float* input  = (const float*)d_in[0];   // [8192,512]
    const int*   adj    = (const int*)d_in[1];     // [8192,8192]
    const float* weight = (const float*)d_in[2];   // [512,256]
    const float* avec   = (const float*)d_in[3];   // [512,1]
    float* out = (float*)d_out;                    // [8192,256]

    cudaFuncSetAttribute((const void*)k_attn,
                         cudaFuncAttributeMaxDynamicSharedMemorySize, ATT_SMEM);

    k_gemm_wh<<<dim3(2, 64), 256>>>(input, weight);
    k_rowdots<<<NROWS / 8, 256>>>(avec);
    k_attn<<<NROWS / 64, 256, ATT_SMEM>>>(adj, out);
}